// round 10
// baseline (speedup 1.0000x reference)
#include <cuda_runtime.h>
#include <cuda_bf16.h>
#include <math.h>
#include <stdint.h>

#define NB 8
#define NP 1024
#define ND 64
#define GAMMA 10.0f
#define MARGIN 0.1f
#define QSCALE 65535.0f
#define IQSCALE (1.0f / 65535.0f)
#define NUNITS 592               // 16 slices x 37 chunks (28 rows each)

// ================= device scratch =================
__device__ __nv_bfloat16 d_hi[6 * NB * NP * ND];
__device__ __nv_bfloat16 d_lo[6 * NB * NP * ND];
__device__ float d_C[NB * NP * NP];                  // sim S (32 MB), dead after finalize
__device__ unsigned short d_Cq[NB * NP * NP];        // u16 cost (16 MB)
__device__ unsigned short d_CTq[NB * NP * NP];       // u16 transposed cost (16 MB)
__device__ float d_r[NB * NP];
__device__ float d_c[NB * NP];
__device__ float d_fs[NB * NP];                      // init row sums  e^{-C/9}
__device__ float d_gs[NB * NP];                      // init col sums  e^{-C/9}
__device__ float d_f[2][NB * NP];
__device__ float d_g[2][NB * NP];
__device__ double d_hinge;
__device__ double d_scon;
__device__ unsigned int d_barcnt = 0;
__device__ unsigned int d_bargen = 0;

// ================= helpers =================
__device__ __forceinline__ uint32_t smem_u32(const void* p) {
    uint32_t a;
    asm("{ .reg .u64 t; cvta.to.shared.u64 t, %1; cvt.u32.u64 %0, t; }" : "=r"(a) : "l"(p));
    return a;
}
__device__ __forceinline__ uint32_t sw128(uint32_t off) { return off ^ ((off >> 3) & 0x70); }

__device__ __forceinline__ void ldsm_x4(uint32_t* r, uint32_t addr) {
    asm volatile("ldmatrix.sync.aligned.m8n8.x4.shared.b16 {%0,%1,%2,%3}, [%4];"
        : "=r"(r[0]), "=r"(r[1]), "=r"(r[2]), "=r"(r[3]) : "r"(addr));
}
__device__ __forceinline__ void ldsm_x2(uint32_t* r, uint32_t addr) {
    asm volatile("ldmatrix.sync.aligned.m8n8.x2.shared.b16 {%0,%1}, [%2];"
        : "=r"(r[0]), "=r"(r[1]) : "r"(addr));
}
__device__ __forceinline__ void mma_bf16(float* d, const uint32_t* a, const uint32_t* b) {
    asm volatile("mma.sync.aligned.m16n8k16.row.col.f32.bf16.bf16.f32 "
        "{%0,%1,%2,%3}, {%4,%5,%6,%7}, {%8,%9}, {%0,%1,%2,%3};"
        : "+f"(d[0]), "+f"(d[1]), "+f"(d[2]), "+f"(d[3])
        : "r"(a[0]), "r"(a[1]), "r"(a[2]), "r"(a[3]), "r"(b[0]), "r"(b[1]));
}
__device__ __forceinline__ unsigned short quant(float v) {
    return (unsigned short)__float2uint_rn(fminf(fmaxf(v, 0.f), 1.f) * QSCALE);
}

// software grid barrier over gridDim.x co-resident blocks (guaranteed by host occupancy calc)
__device__ __forceinline__ void grid_barrier() {
    __syncthreads();
    if (threadIdx.x == 0) {
        __threadfence();
        unsigned int gen = *((volatile unsigned int*)&d_bargen);
        unsigned int t = atomicAdd(&d_barcnt, 1);
        if (t == gridDim.x - 1) {
            atomicExch(&d_barcnt, 0u);
            __threadfence();
            atomicExch(&d_bargen, gen + 1);
        } else {
            while (*((volatile unsigned int*)&d_bargen) == gen) __nanosleep(64);
        }
        __threadfence();
    }
    __syncthreads();
}

// ================= reset =================
__global__ void reset_kernel() {
    int i = blockIdx.x * blockDim.x + threadIdx.x;
    if (i < NB * NP) { d_r[i] = 0.f; d_c[i] = 0.f; d_fs[i] = 0.f; d_gs[i] = 0.f; }
    if (i == 0) { d_hinge = 0.0; d_scon = 0.0; }
}

// ================= normalize + hi/lo split =================
__global__ void norm_split(const float* __restrict__ x1, const float* __restrict__ x2,
                           const float* __restrict__ x3, const float* __restrict__ x4) {
    int w = (blockIdx.x * blockDim.x + threadIdx.x) >> 5;
    int lane = threadIdx.x & 31;
    int t = w / 8192;
    int row = w - t * 8192;
    const float* src = (t == 0) ? x1 : (t == 1) ? x2 : (t == 2 || t == 4) ? x3 : x4;
    float2 v = ((const float2*)(src + (size_t)row * ND))[lane];
    if (t < 4) {
        float ss = v.x * v.x + v.y * v.y;
        #pragma unroll
        for (int o = 16; o; o >>= 1) ss += __shfl_xor_sync(0xFFFFFFFFu, ss, o);
        float sc = 1.0f / fmaxf(sqrtf(ss), 1e-12f);
        v.x *= sc; v.y *= sc;
    }
    __nv_bfloat16 hx = __float2bfloat16(v.x);
    __nv_bfloat16 hy = __float2bfloat16(v.y);
    size_t base = ((size_t)t * 8192 + row) * ND;
    ((__nv_bfloat162*)(d_hi + base))[lane] = __nv_bfloat162(hx, hy);
    if (t < 4) {
        __nv_bfloat16 lx = __float2bfloat16(v.x - __bfloat162float(hx));
        __nv_bfloat16 ly = __float2bfloat16(v.y - __bfloat162float(hy));
        ((__nv_bfloat162*)(d_lo + base))[lane] = __nv_bfloat162(lx, ly);
    }
}

// ================= mma.sync fused GEMM (unchanged from R8) =================
#define SM_AHI  0
#define SM_ALO  16384
#define SM_BHI  32768
#define SM_BLO  49152
#define SM_RED  65536
#define SM_TOT  (65536 + 256)

__global__ void __launch_bounds__(256, 2) mma_gemm() {
    extern __shared__ char smem[];
    uint32_t sb = smem_u32(smem);
    int tid = threadIdx.x;
    int wid = tid >> 5;
    int lane = tid & 31;
    int warp_m = wid >> 2;
    int warp_n = wid & 3;
    int z = blockIdx.z;
    int b = z & 7;
    int job = z >> 3;
    int rowBase = blockIdx.y * 128;
    int colBase = blockIdx.x * 128;

    const int TA[4] = {0, 0, 2, 4};
    const int TB[4] = {1, 3, 1, 5};
    {
        size_t aoff = ((size_t)TA[job] * 8192 + b * NP + rowBase) * ND;
        size_t boff = ((size_t)TB[job] * 8192 + b * NP + colBase) * ND;
        const uint4* sA = (const uint4*)(d_hi + aoff);
        const uint4* sB = (const uint4*)(d_hi + boff);
        #pragma unroll
        for (int it = 0; it < 4; it++) {
            int idx = it * 256 + tid;
            int r = idx >> 3, c = idx & 7;
            uint32_t so = sw128(r * 128 + c * 16);
            *(uint4*)(smem + SM_AHI + so) = sA[idx];
            *(uint4*)(smem + SM_BHI + so) = sB[idx];
        }
        if (job != 3) {
            const uint4* sAl = (const uint4*)(d_lo + aoff);
            const uint4* sBl = (const uint4*)(d_lo + boff);
            #pragma unroll
            for (int it = 0; it < 4; it++) {
                int idx = it * 256 + tid;
                int r = idx >> 3, c = idx & 7;
                uint32_t so = sw128(r * 128 + c * 16);
                *(uint4*)(smem + SM_ALO + so) = sAl[idx];
                *(uint4*)(smem + SM_BLO + so) = sBl[idx];
            }
        }
    }
    __syncthreads();

    float acc[4][4][4];
    #pragma unroll
    for (int mi = 0; mi < 4; mi++)
        #pragma unroll
        for (int ni = 0; ni < 4; ni++)
            #pragma unroll
            for (int v = 0; v < 4; v++) acc[mi][ni][v] = 0.f;

    int mrow = warp_m * 64 + (lane & 15);
    int nrow = warp_n * 32 + (lane & 7);
    int l7 = lane & 7;

    #pragma unroll
    for (int k = 0; k < 4; k++) {
        uint32_t Af[4][4], Bh[4][2], Bl[4][2];
        int achunk = (2 * k + (lane >> 4)) ^ l7;
        int bchunk = (2 * k + ((lane >> 3) & 1)) ^ l7;
        #pragma unroll
        for (int mi = 0; mi < 4; mi++)
            ldsm_x4(Af[mi], sb + SM_AHI + (mrow + mi * 16) * 128 + achunk * 16);
        #pragma unroll
        for (int ni = 0; ni < 4; ni++)
            ldsm_x2(Bh[ni], sb + SM_BHI + (nrow + ni * 8) * 128 + bchunk * 16);
        #pragma unroll
        for (int mi = 0; mi < 4; mi++)
            #pragma unroll
            for (int ni = 0; ni < 4; ni++)
                mma_bf16(acc[mi][ni], Af[mi], Bh[ni]);           // hi*hi
        if (job != 3) {
            #pragma unroll
            for (int ni = 0; ni < 4; ni++)
                ldsm_x2(Bl[ni], sb + SM_BLO + (nrow + ni * 8) * 128 + bchunk * 16);
            #pragma unroll
            for (int mi = 0; mi < 4; mi++)
                #pragma unroll
                for (int ni = 0; ni < 4; ni++)
                    mma_bf16(acc[mi][ni], Af[mi], Bl[ni]);       // hi*lo
            #pragma unroll
            for (int mi = 0; mi < 4; mi++)
                ldsm_x4(Af[mi], sb + SM_ALO + (mrow + mi * 16) * 128 + achunk * 16);
            #pragma unroll
            for (int mi = 0; mi < 4; mi++)
                #pragma unroll
                for (int ni = 0; ni < 4; ni++)
                    mma_bf16(acc[mi][ni], Af[mi], Bh[ni]);       // lo*hi
        }
    }

    int g = lane >> 2, t4 = lane & 3;

    if (job == 3) {
        float h = 0.f;
        #pragma unroll
        for (int mi = 0; mi < 4; mi++)
            #pragma unroll
            for (int ni = 0; ni < 4; ni++)
                #pragma unroll
                for (int v = 0; v < 4; v++)
                    h += fmaxf(MARGIN - acc[mi][ni][v], 0.f);
        #pragma unroll
        for (int o = 16; o; o >>= 1) h += __shfl_xor_sync(0xFFFFFFFFu, h, o);
        float* red = (float*)(smem + SM_RED);
        if (lane == 0) red[wid] = h;
        __syncthreads();
        if (tid == 0) {
            float s = 0.f;
            #pragma unroll
            for (int w = 0; w < 8; w++) s += red[w];
            atomicAdd(&d_hinge, (double)s);
        }
        return;
    }

    float rs[4][2], cs[4][2];
    #pragma unroll
    for (int i = 0; i < 4; i++) { rs[i][0] = rs[i][1] = cs[i][0] = cs[i][1] = 0.f; }

    #pragma unroll
    for (int mi = 0; mi < 4; mi++) {
        int row = rowBase + warp_m * 64 + mi * 16 + g;
        #pragma unroll
        for (int ni = 0; ni < 4; ni++) {
            float e0 = __expf(GAMMA * acc[mi][ni][0]);
            float e1 = __expf(GAMMA * acc[mi][ni][1]);
            float e2 = __expf(GAMMA * acc[mi][ni][2]);
            float e3 = __expf(GAMMA * acc[mi][ni][3]);
            if (job == 0) {
                int col = colBase + warp_n * 32 + ni * 8 + t4 * 2;
                float* Cp = d_C + ((size_t)b * NP + row) * NP + col;
                *(float2*)Cp = make_float2(e0, e1);
                *(float2*)(Cp + (size_t)8 * NP) = make_float2(e2, e3);
            }
            rs[mi][0] += e0 + e1;  rs[mi][1] += e2 + e3;
            cs[ni][0] += e0 + e2;  cs[ni][1] += e1 + e3;
        }
    }

    if (job <= 1) {
        #pragma unroll
        for (int mi = 0; mi < 4; mi++) {
            float r0 = rs[mi][0], r1 = rs[mi][1];
            r0 += __shfl_xor_sync(0xFFFFFFFFu, r0, 1);
            r0 += __shfl_xor_sync(0xFFFFFFFFu, r0, 2);
            r1 += __shfl_xor_sync(0xFFFFFFFFu, r1, 1);
            r1 += __shfl_xor_sync(0xFFFFFFFFu, r1, 2);
            if (t4 == 0) {
                int row = rowBase + warp_m * 64 + mi * 16 + g;
                atomicAdd(&d_r[b * NP + row], r0);
                atomicAdd(&d_r[b * NP + row + 8], r1);
            }
        }
    }
    if (job == 0 || job == 2) {
        #pragma unroll
        for (int ni = 0; ni < 4; ni++) {
            float c0 = cs[ni][0], c1 = cs[ni][1];
            c0 += __shfl_xor_sync(0xFFFFFFFFu, c0, 4);
            c0 += __shfl_xor_sync(0xFFFFFFFFu, c0, 8);
            c0 += __shfl_xor_sync(0xFFFFFFFFu, c0, 16);
            c1 += __shfl_xor_sync(0xFFFFFFFFu, c1, 4);
            c1 += __shfl_xor_sync(0xFFFFFFFFu, c1, 8);
            c1 += __shfl_xor_sync(0xFFFFFFFFu, c1, 16);
            if (lane < 4) {
                int col = colBase + warp_n * 32 + ni * 8 + lane * 2;
                atomicAdd(&d_c[b * NP + col], c0);
                atomicAdd(&d_c[b * NP + col + 1], c1);
            }
        }
    }
}

// ================= finalize: C -> u16 Cq/CTq + fused init-softmin sums =================
__global__ void finalize_kernel() {
    __shared__ float tile[64][68];
    __shared__ float scol[64];
    int b = blockIdx.z;
    int pBase = blockIdx.y * 64, qBase = blockIdx.x * 64;
    int tid = threadIdx.x;  // 256
    int lane = tid & 31;
    const float NK9 = -0.16029948f;   // -log2(e)/9
    float cpart[4] = {0.f, 0.f, 0.f, 0.f};
    float rpart[4];
    if (tid < 64) scol[tid] = 0.f;
    __syncthreads();
    #pragma unroll
    for (int v = 0; v < 4; v++) {
        int f4 = v * 256 + tid;
        int row = f4 >> 4;
        int c4 = f4 & 15;
        int p = pBase + row;
        size_t idx = ((size_t)b * NP + p) * NP + qBase + c4 * 4;
        float4 S = *(const float4*)(d_C + idx);
        float rp = d_r[b * NP + p];
        float4 cq = *(const float4*)(d_c + b * NP + qBase + c4 * 4);
        float4 C;
        C.x = 1.f - __fdividef(S.x, rp + cq.x - S.x);
        C.y = 1.f - __fdividef(S.y, rp + cq.y - S.y);
        C.z = 1.f - __fdividef(S.z, rp + cq.z - S.z);
        C.w = 1.f - __fdividef(S.w, rp + cq.w - S.w);
        ushort4 q = make_ushort4(quant(C.x), quant(C.y), quant(C.z), quant(C.w));
        *(ushort4*)(d_Cq + idx) = q;
        *(float4*)&tile[row][c4 * 4] = C;
        float e0 = exp2f(C.x * NK9);
        float e1 = exp2f(C.y * NK9);
        float e2 = exp2f(C.z * NK9);
        float e3 = exp2f(C.w * NK9);
        rpart[v] = (e0 + e1) + (e2 + e3);
        cpart[0] += e0; cpart[1] += e1; cpart[2] += e2; cpart[3] += e3;
    }
    #pragma unroll
    for (int v = 0; v < 4; v++) {
        float r = rpart[v];
        r += __shfl_xor_sync(0xFFFFFFFFu, r, 1);
        r += __shfl_xor_sync(0xFFFFFFFFu, r, 2);
        r += __shfl_xor_sync(0xFFFFFFFFu, r, 4);
        r += __shfl_xor_sync(0xFFFFFFFFu, r, 8);
        if ((lane & 15) == 0)
            atomicAdd(&d_fs[b * NP + pBase + v * 16 + (tid >> 4)], r);
    }
    #pragma unroll
    for (int j = 0; j < 4; j++) {
        cpart[j] += __shfl_xor_sync(0xFFFFFFFFu, cpart[j], 16);
        if (lane < 16) atomicAdd(&scol[lane * 4 + j], cpart[j]);
    }
    __syncthreads();
    if (tid < 64) atomicAdd(&d_gs[b * NP + qBase + tid], scol[tid]);

    #pragma unroll
    for (int v = 0; v < 4; v++) {
        int f4 = v * 256 + tid;
        int qr = f4 >> 4;
        int p4 = f4 & 15;
        ushort4 o;
        o.x = quant(tile[p4 * 4 + 0][qr]);
        o.y = quant(tile[p4 * 4 + 1][qr]);
        o.z = quant(tile[p4 * 4 + 2][qr]);
        o.w = quant(tile[p4 * 4 + 3][qr]);
        *(ushort4*)(d_CTq + ((size_t)b * NP + qBase + qr) * NP + pBase + p4 * 4) = o;
    }
}

// ================= persistent Sinkhorn: dynamic units, occupancy-safe grid =================
struct EpsList { float e[8]; };

__global__ void __launch_bounds__(256, 4) sinkhorn_persist(EpsList el) {
    __shared__ float hs[NP];
    __shared__ float bred[8];
    int tid = threadIdx.x, wid = tid >> 5, lane = tid & 31;
    const float ELN2 = 0.69314718055994531f;
    float scon_acc = 0.f;

    for (int it = 0; it < 9; it++) {
        bool fin = (it == 8);
        float eps = fin ? el.e[7] : el.e[it];
        bool init = (it == 0);
        bool umax = (eps < 0.02f);
        int src = fin ? 0 : (it & 1);
        int dst = 1 - (it & 1);
        float k2 = 1.4426950408889634f / eps;
        float qk = -IQSCALE * k2;

        // dynamic unit loop: unit = (slice, 28-row chunk)
        for (int u = blockIdx.x; u < NUNITS; u += gridDim.x) {
            int slice = u / 37;
            int bsl = u - slice * 37;
            int side = slice >> 3, b = slice & 7;
            int rowbase = bsl * 28;
            const unsigned short* Cb = (side == 0 ? d_Cq : d_CTq) + (size_t)b * NP * NP;

            const float* hsrc = (side == 0 ? (init ? d_gs : d_g[src])
                                           : (init ? d_fs : d_f[src])) + b * NP;
            for (int i = tid; i < NP; i += 256) {
                float h = __ldcg(&hsrc[i]);
                if (init) h = -9.0f * __logf(h);
                hs[i] = h * k2;
            }
            __syncthreads();
            const float4* h4 = (const float4*)hs;

            #pragma unroll 1
            for (int j = 0; j < 4; j++) {
                int rofs = wid + 8 * j;
                int row = rowbase + rofs;
                if (rofs < 28 && row < NP) {
                    const uint4* rowp = (const uint4*)(Cb + (size_t)row * NP);
                    float m = 0.f;
                    if (umax) {
                        float mm = -3.4e38f;
                        #pragma unroll
                        for (int jj = 0; jj < 4; jj++) {
                            uint4 q = rowp[jj * 32 + lane];
                            float4 h0 = h4[(jj * 32 + lane) * 2];
                            float4 h1 = h4[(jj * 32 + lane) * 2 + 1];
                            mm = fmaxf(mm, fmaf((float)(q.x & 0xFFFF), qk, h0.x));
                            mm = fmaxf(mm, fmaf((float)(q.x >> 16),    qk, h0.y));
                            mm = fmaxf(mm, fmaf((float)(q.y & 0xFFFF), qk, h0.z));
                            mm = fmaxf(mm, fmaf((float)(q.y >> 16),    qk, h0.w));
                            mm = fmaxf(mm, fmaf((float)(q.z & 0xFFFF), qk, h1.x));
                            mm = fmaxf(mm, fmaf((float)(q.z >> 16),    qk, h1.y));
                            mm = fmaxf(mm, fmaf((float)(q.w & 0xFFFF), qk, h1.z));
                            mm = fmaxf(mm, fmaf((float)(q.w >> 16),    qk, h1.w));
                        }
                        #pragma unroll
                        for (int o = 16; o; o >>= 1)
                            mm = fmaxf(mm, __shfl_xor_sync(0xFFFFFFFFu, mm, o));
                        m = mm;
                    }
                    float s0 = 0, s1 = 0, s2 = 0, s3 = 0;
                    #pragma unroll
                    for (int jj = 0; jj < 4; jj++) {
                        uint4 q = rowp[jj * 32 + lane];
                        float4 h0 = h4[(jj * 32 + lane) * 2];
                        float4 h1 = h4[(jj * 32 + lane) * 2 + 1];
                        s0 += exp2f(fmaf((float)(q.x & 0xFFFF), qk, h0.x) - m);
                        s1 += exp2f(fmaf((float)(q.x >> 16),    qk, h0.y) - m);
                        s2 += exp2f(fmaf((float)(q.y & 0xFFFF), qk, h0.z) - m);
                        s3 += exp2f(fmaf((float)(q.y >> 16),    qk, h0.w) - m);
                        s0 += exp2f(fmaf((float)(q.z & 0xFFFF), qk, h1.x) - m);
                        s1 += exp2f(fmaf((float)(q.z >> 16),    qk, h1.y) - m);
                        s2 += exp2f(fmaf((float)(q.w & 0xFFFF), qk, h1.z) - m);
                        s3 += exp2f(fmaf((float)(q.w >> 16),    qk, h1.w) - m);
                    }
                    float sum = (s0 + s1) + (s2 + s3);
                    #pragma unroll
                    for (int o = 16; o; o >>= 1) sum += __shfl_xor_sync(0xFFFFFFFFu, sum, o);

                    if (lane == 0) {
                        float val = -eps * ELN2 * (m + __log2f(sum));
                        if (fin) {
                            scon_acc += val;
                        } else {
                            float prev;
                            if (init) prev = -9.0f * __logf(__ldcg(&((side == 0 ? d_fs : d_gs)[b * NP + row])));
                            else      prev = __ldcg(&((side == 0 ? d_f[src] : d_g[src])[b * NP + row]));
                            val = 0.5f * (prev + val);
                            (side == 0 ? d_f[dst] : d_g[dst])[b * NP + row] = val;
                        }
                    }
                }
            }
            __syncthreads();   // protect hs before next unit overwrites it
        }
        if (!fin) {
            __threadfence();
            grid_barrier();
        }
    }

    if (lane == 0) bred[wid] = scon_acc;
    __syncthreads();
    if (tid == 0) {
        float s = ((bred[0] + bred[1]) + (bred[2] + bred[3]))
                + ((bred[4] + bred[5]) + (bred[6] + bred[7]));
        atomicAdd(&d_scon, (double)s);
    }
}

// ================= output =================
__global__ void write_out(float* out) {
    if (threadIdx.x == 0) {
        out[0] = (float)d_hinge;
        out[1] = (float)(d_scon / 8.0);
    }
}

// ================= launch =================
extern "C" void kernel_launch(void* const* d_in, const int* in_sizes, int n_in,
                              void* d_out, int out_size) {
    (void)in_sizes; (void)n_in; (void)out_size;
    const float* x1 = (const float*)d_in[0];
    const float* x2 = (const float*)d_in[1];
    const float* x3 = (const float*)d_in[2];
    const float* x4 = (const float*)d_in[3];
    float* out = (float*)d_out;

    double pexp = 2.0, diam = 3.0, blur = 0.05, scal = 0.5;
    EpsList el;
    int n_eps = 0;
    el.e[n_eps++] = (float)pow(diam, pexp);
    for (double v = pexp * log(diam); v > pexp * log(blur); v += pexp * log(scal))
        el.e[n_eps++] = (float)exp(v);
    el.e[n_eps++] = (float)pow(blur, pexp);   // n_eps == 8

    cudaFuncSetAttribute(mma_gemm, cudaFuncAttributeMaxDynamicSharedMemorySize, SM_TOT);

    // occupancy-safe persistent grid (deadlock-proof by construction)
    int dev = 0, sms = 0, maxb = 0;
    cudaGetDevice(&dev);
    cudaDeviceGetAttribute(&sms, cudaDevAttrMultiProcessorCount, dev);
    cudaOccupancyMaxActiveBlocksPerMultiprocessor(&maxb, sinkhorn_persist, 256, 0);
    if (sms < 1) sms = 1;
    if (maxb < 1) maxb = 1;
    int G = sms * maxb;
    if (G > NUNITS) G = NUNITS;

    reset_kernel<<<32, 256>>>();
    norm_split<<<6144, 256>>>(x1, x2, x3, x4);

    mma_gemm<<<dim3(8, 8, 32), 256, SM_TOT>>>();

    finalize_kernel<<<dim3(16, 16, NB), 256>>>();   // also produces init sums

    sinkhorn_persist<<<G, 256>>>(el);               // 8 sweeps + final extrapolation

    write_out<<<1, 1>>>(out);
}

// round 11
// speedup vs baseline: 1.1535x; 1.1535x over previous
#include <cuda_runtime.h>
#include <cuda_bf16.h>
#include <math.h>
#include <stdint.h>

#define NB 8
#define NP 1024
#define ND 64
#define GAMMA 10.0f
#define MARGIN 0.1f
#define QSCALE 65535.0f
#define IQSCALE (1.0f / 65535.0f)

// ================= device scratch =================
__device__ __nv_bfloat16 d_hi[6 * NB * NP * ND];
__device__ __nv_bfloat16 d_lo[6 * NB * NP * ND];
__device__ float d_C[NB * NP * NP];                  // sim S (32 MB), dead after finalize
__device__ unsigned short d_Cq[NB * NP * NP];        // u16 cost (16 MB)
__device__ unsigned short d_CTq[NB * NP * NP];       // u16 transposed cost (16 MB)
__device__ float d_r[NB * NP];
__device__ float d_c[NB * NP];
__device__ float d_fs[NB * NP];                      // init row sums  e^{-C/9}
__device__ float d_gs[NB * NP];                      // init col sums  e^{-C/9}
__device__ float d_f[2][NB * NP];
__device__ float d_g[2][NB * NP];
__device__ double d_hinge;
__device__ double d_scon;

// ================= helpers =================
__device__ __forceinline__ uint32_t smem_u32(const void* p) {
    uint32_t a;
    asm("{ .reg .u64 t; cvta.to.shared.u64 t, %1; cvt.u32.u64 %0, t; }" : "=r"(a) : "l"(p));
    return a;
}
__device__ __forceinline__ uint32_t sw128(uint32_t off) { return off ^ ((off >> 3) & 0x70); }

__device__ __forceinline__ void ldsm_x4(uint32_t* r, uint32_t addr) {
    asm volatile("ldmatrix.sync.aligned.m8n8.x4.shared.b16 {%0,%1,%2,%3}, [%4];"
        : "=r"(r[0]), "=r"(r[1]), "=r"(r[2]), "=r"(r[3]) : "r"(addr));
}
__device__ __forceinline__ void ldsm_x2(uint32_t* r, uint32_t addr) {
    asm volatile("ldmatrix.sync.aligned.m8n8.x2.shared.b16 {%0,%1}, [%2];"
        : "=r"(r[0]), "=r"(r[1]) : "r"(addr));
}
__device__ __forceinline__ void mma_bf16(float* d, const uint32_t* a, const uint32_t* b) {
    asm volatile("mma.sync.aligned.m16n8k16.row.col.f32.bf16.bf16.f32 "
        "{%0,%1,%2,%3}, {%4,%5,%6,%7}, {%8,%9}, {%0,%1,%2,%3};"
        : "+f"(d[0]), "+f"(d[1]), "+f"(d[2]), "+f"(d[3])
        : "r"(a[0]), "r"(a[1]), "r"(a[2]), "r"(a[3]), "r"(b[0]), "r"(b[1]));
}
__device__ __forceinline__ unsigned short quant(float v) {
    return (unsigned short)__float2uint_rn(fminf(fmaxf(v, 0.f), 1.f) * QSCALE);
}

// ================= normalize + hi/lo split (block 6144 = reset) =================
__global__ void norm_split(const float* __restrict__ x1, const float* __restrict__ x2,
                           const float* __restrict__ x3, const float* __restrict__ x4) {
    if (blockIdx.x == 6144) {
        int tid = threadIdx.x;
        for (int i = tid; i < NB * NP; i += 256) {
            d_r[i] = 0.f; d_c[i] = 0.f; d_fs[i] = 0.f; d_gs[i] = 0.f;
        }
        if (tid == 0) { d_hinge = 0.0; d_scon = 0.0; }
        return;
    }
    int w = (blockIdx.x * 256 + threadIdx.x) >> 5;
    int lane = threadIdx.x & 31;
    int t = w / 8192;
    int row = w - t * 8192;
    const float* src = (t == 0) ? x1 : (t == 1) ? x2 : (t == 2 || t == 4) ? x3 : x4;
    float2 v = ((const float2*)(src + (size_t)row * ND))[lane];
    if (t < 4) {
        float ss = v.x * v.x + v.y * v.y;
        #pragma unroll
        for (int o = 16; o; o >>= 1) ss += __shfl_xor_sync(0xFFFFFFFFu, ss, o);
        float sc = 1.0f / fmaxf(sqrtf(ss), 1e-12f);
        v.x *= sc; v.y *= sc;
    }
    __nv_bfloat16 hx = __float2bfloat16(v.x);
    __nv_bfloat16 hy = __float2bfloat16(v.y);
    size_t base = ((size_t)t * 8192 + row) * ND;
    ((__nv_bfloat162*)(d_hi + base))[lane] = __nv_bfloat162(hx, hy);
    if (t < 4) {
        __nv_bfloat16 lx = __float2bfloat16(v.x - __bfloat162float(hx));
        __nv_bfloat16 ly = __float2bfloat16(v.y - __bfloat162float(hy));
        ((__nv_bfloat162*)(d_lo + base))[lane] = __nv_bfloat162(lx, ly);
    }
}

// ================= mma.sync fused GEMM (unchanged from R8) =================
#define SM_AHI  0
#define SM_ALO  16384
#define SM_BHI  32768
#define SM_BLO  49152
#define SM_RED  65536
#define SM_TOT  (65536 + 256)

__global__ void __launch_bounds__(256, 2) mma_gemm() {
    extern __shared__ char smem[];
    uint32_t sb = smem_u32(smem);
    int tid = threadIdx.x;
    int wid = tid >> 5;
    int lane = tid & 31;
    int warp_m = wid >> 2;
    int warp_n = wid & 3;
    int z = blockIdx.z;
    int b = z & 7;
    int job = z >> 3;
    int rowBase = blockIdx.y * 128;
    int colBase = blockIdx.x * 128;

    const int TA[4] = {0, 0, 2, 4};
    const int TB[4] = {1, 3, 1, 5};
    {
        size_t aoff = ((size_t)TA[job] * 8192 + b * NP + rowBase) * ND;
        size_t boff = ((size_t)TB[job] * 8192 + b * NP + colBase) * ND;
        const uint4* sA = (const uint4*)(d_hi + aoff);
        const uint4* sB = (const uint4*)(d_hi + boff);
        #pragma unroll
        for (int it = 0; it < 4; it++) {
            int idx = it * 256 + tid;
            int r = idx >> 3, c = idx & 7;
            uint32_t so = sw128(r * 128 + c * 16);
            *(uint4*)(smem + SM_AHI + so) = sA[idx];
            *(uint4*)(smem + SM_BHI + so) = sB[idx];
        }
        if (job != 3) {
            const uint4* sAl = (const uint4*)(d_lo + aoff);
            const uint4* sBl = (const uint4*)(d_lo + boff);
            #pragma unroll
            for (int it = 0; it < 4; it++) {
                int idx = it * 256 + tid;
                int r = idx >> 3, c = idx & 7;
                uint32_t so = sw128(r * 128 + c * 16);
                *(uint4*)(smem + SM_ALO + so) = sAl[idx];
                *(uint4*)(smem + SM_BLO + so) = sBl[idx];
            }
        }
    }
    __syncthreads();

    float acc[4][4][4];
    #pragma unroll
    for (int mi = 0; mi < 4; mi++)
        #pragma unroll
        for (int ni = 0; ni < 4; ni++)
            #pragma unroll
            for (int v = 0; v < 4; v++) acc[mi][ni][v] = 0.f;

    int mrow = warp_m * 64 + (lane & 15);
    int nrow = warp_n * 32 + (lane & 7);
    int l7 = lane & 7;

    #pragma unroll
    for (int k = 0; k < 4; k++) {
        uint32_t Af[4][4], Bh[4][2], Bl[4][2];
        int achunk = (2 * k + (lane >> 4)) ^ l7;
        int bchunk = (2 * k + ((lane >> 3) & 1)) ^ l7;
        #pragma unroll
        for (int mi = 0; mi < 4; mi++)
            ldsm_x4(Af[mi], sb + SM_AHI + (mrow + mi * 16) * 128 + achunk * 16);
        #pragma unroll
        for (int ni = 0; ni < 4; ni++)
            ldsm_x2(Bh[ni], sb + SM_BHI + (nrow + ni * 8) * 128 + bchunk * 16);
        #pragma unroll
        for (int mi = 0; mi < 4; mi++)
            #pragma unroll
            for (int ni = 0; ni < 4; ni++)
                mma_bf16(acc[mi][ni], Af[mi], Bh[ni]);           // hi*hi
        if (job != 3) {
            #pragma unroll
            for (int ni = 0; ni < 4; ni++)
                ldsm_x2(Bl[ni], sb + SM_BLO + (nrow + ni * 8) * 128 + bchunk * 16);
            #pragma unroll
            for (int mi = 0; mi < 4; mi++)
                #pragma unroll
                for (int ni = 0; ni < 4; ni++)
                    mma_bf16(acc[mi][ni], Af[mi], Bl[ni]);       // hi*lo
            #pragma unroll
            for (int mi = 0; mi < 4; mi++)
                ldsm_x4(Af[mi], sb + SM_ALO + (mrow + mi * 16) * 128 + achunk * 16);
            #pragma unroll
            for (int mi = 0; mi < 4; mi++)
                #pragma unroll
                for (int ni = 0; ni < 4; ni++)
                    mma_bf16(acc[mi][ni], Af[mi], Bh[ni]);       // lo*hi
        }
    }

    int g = lane >> 2, t4 = lane & 3;

    if (job == 3) {
        float h = 0.f;
        #pragma unroll
        for (int mi = 0; mi < 4; mi++)
            #pragma unroll
            for (int ni = 0; ni < 4; ni++)
                #pragma unroll
                for (int v = 0; v < 4; v++)
                    h += fmaxf(MARGIN - acc[mi][ni][v], 0.f);
        #pragma unroll
        for (int o = 16; o; o >>= 1) h += __shfl_xor_sync(0xFFFFFFFFu, h, o);
        float* red = (float*)(smem + SM_RED);
        if (lane == 0) red[wid] = h;
        __syncthreads();
        if (tid == 0) {
            float s = 0.f;
            #pragma unroll
            for (int w = 0; w < 8; w++) s += red[w];
            atomicAdd(&d_hinge, (double)s);
        }
        return;
    }

    float rs[4][2], cs[4][2];
    #pragma unroll
    for (int i = 0; i < 4; i++) { rs[i][0] = rs[i][1] = cs[i][0] = cs[i][1] = 0.f; }

    #pragma unroll
    for (int mi = 0; mi < 4; mi++) {
        int row = rowBase + warp_m * 64 + mi * 16 + g;
        #pragma unroll
        for (int ni = 0; ni < 4; ni++) {
            float e0 = __expf(GAMMA * acc[mi][ni][0]);
            float e1 = __expf(GAMMA * acc[mi][ni][1]);
            float e2 = __expf(GAMMA * acc[mi][ni][2]);
            float e3 = __expf(GAMMA * acc[mi][ni][3]);
            if (job == 0) {
                int col = colBase + warp_n * 32 + ni * 8 + t4 * 2;
                float* Cp = d_C + ((size_t)b * NP + row) * NP + col;
                *(float2*)Cp = make_float2(e0, e1);
                *(float2*)(Cp + (size_t)8 * NP) = make_float2(e2, e3);
            }
            rs[mi][0] += e0 + e1;  rs[mi][1] += e2 + e3;
            cs[ni][0] += e0 + e2;  cs[ni][1] += e1 + e3;
        }
    }

    if (job <= 1) {
        #pragma unroll
        for (int mi = 0; mi < 4; mi++) {
            float r0 = rs[mi][0], r1 = rs[mi][1];
            r0 += __shfl_xor_sync(0xFFFFFFFFu, r0, 1);
            r0 += __shfl_xor_sync(0xFFFFFFFFu, r0, 2);
            r1 += __shfl_xor_sync(0xFFFFFFFFu, r1, 1);
            r1 += __shfl_xor_sync(0xFFFFFFFFu, r1, 2);
            if (t4 == 0) {
                int row = rowBase + warp_m * 64 + mi * 16 + g;
                atomicAdd(&d_r[b * NP + row], r0);
                atomicAdd(&d_r[b * NP + row + 8], r1);
            }
        }
    }
    if (job == 0 || job == 2) {
        #pragma unroll
        for (int ni = 0; ni < 4; ni++) {
            float c0 = cs[ni][0], c1 = cs[ni][1];
            c0 += __shfl_xor_sync(0xFFFFFFFFu, c0, 4);
            c0 += __shfl_xor_sync(0xFFFFFFFFu, c0, 8);
            c0 += __shfl_xor_sync(0xFFFFFFFFu, c0, 16);
            c1 += __shfl_xor_sync(0xFFFFFFFFu, c1, 4);
            c1 += __shfl_xor_sync(0xFFFFFFFFu, c1, 8);
            c1 += __shfl_xor_sync(0xFFFFFFFFu, c1, 16);
            if (lane < 4) {
                int col = colBase + warp_n * 32 + ni * 8 + lane * 2;
                atomicAdd(&d_c[b * NP + col], c0);
                atomicAdd(&d_c[b * NP + col + 1], c1);
            }
        }
    }
}

// ================= finalize: C -> u16 Cq/CTq + fused init sums (u16 tile, conflict-free) ====
__global__ void finalize_kernel() {
    __shared__ unsigned short tile[64][74];   // 9.5 KB; word-stride 37 (odd)
    __shared__ float scol[64];
    int b = blockIdx.z;
    int pBase = blockIdx.y * 64, qBase = blockIdx.x * 64;
    int tid = threadIdx.x;  // 256
    int lane = tid & 31;
    const float NK9 = -0.16029948f;   // -log2(e)/9
    float cpart[4] = {0.f, 0.f, 0.f, 0.f};
    float rpart[4];
    if (tid < 64) scol[tid] = 0.f;
    __syncthreads();
    #pragma unroll
    for (int v = 0; v < 4; v++) {
        int f4 = v * 256 + tid;
        int row = f4 >> 4;
        int c4 = f4 & 15;
        int p = pBase + row;
        size_t idx = ((size_t)b * NP + p) * NP + qBase + c4 * 4;
        float4 S = *(const float4*)(d_C + idx);
        float rp = d_r[b * NP + p];
        float4 cq = *(const float4*)(d_c + b * NP + qBase + c4 * 4);
        float4 C;
        C.x = 1.f - __fdividef(S.x, rp + cq.x - S.x);
        C.y = 1.f - __fdividef(S.y, rp + cq.y - S.y);
        C.z = 1.f - __fdividef(S.z, rp + cq.z - S.z);
        C.w = 1.f - __fdividef(S.w, rp + cq.w - S.w);
        ushort4 q = make_ushort4(quant(C.x), quant(C.y), quant(C.z), quant(C.w));
        *(ushort4*)(d_Cq + idx) = q;
        ((ushort2*)&tile[row][c4 * 4])[0] = make_ushort2(q.x, q.y);
        ((ushort2*)&tile[row][c4 * 4])[1] = make_ushort2(q.z, q.w);
        float e0 = exp2f(C.x * NK9);
        float e1 = exp2f(C.y * NK9);
        float e2 = exp2f(C.z * NK9);
        float e3 = exp2f(C.w * NK9);
        rpart[v] = (e0 + e1) + (e2 + e3);
        cpart[0] += e0; cpart[1] += e1; cpart[2] += e2; cpart[3] += e3;
    }
    #pragma unroll
    for (int v = 0; v < 4; v++) {
        float r = rpart[v];
        r += __shfl_xor_sync(0xFFFFFFFFu, r, 1);
        r += __shfl_xor_sync(0xFFFFFFFFu, r, 2);
        r += __shfl_xor_sync(0xFFFFFFFFu, r, 4);
        r += __shfl_xor_sync(0xFFFFFFFFu, r, 8);
        if ((lane & 15) == 0)
            atomicAdd(&d_fs[b * NP + pBase + v * 16 + (tid >> 4)], r);
    }
    #pragma unroll
    for (int j = 0; j < 4; j++) {
        cpart[j] += __shfl_xor_sync(0xFFFFFFFFu, cpart[j], 16);
        if (lane < 16) atomicAdd(&scol[lane * 4 + j], cpart[j]);
    }
    __syncthreads();
    if (tid < 64) atomicAdd(&d_gs[b * NP + qBase + tid], scol[tid]);

    // phase 2: conflict-free u16 transpose -> CTq (uint4 stores)
    int q = tid >> 2;       // 0..63
    int sbase = tid & 3;    // 0..3
    #pragma unroll
    for (int cc0 = 0; cc0 < 2; cc0++) {
        int cc = sbase + cc0 * 4;     // chunk 0..7
        int p0 = cc * 8;
        unsigned short v16[8];
        #pragma unroll
        for (int i = 0; i < 8; i++) v16[i] = tile[p0 + i][q];
        uint4 o;
        o.x = (uint32_t)v16[0] | ((uint32_t)v16[1] << 16);
        o.y = (uint32_t)v16[2] | ((uint32_t)v16[3] << 16);
        o.z = (uint32_t)v16[4] | ((uint32_t)v16[5] << 16);
        o.w = (uint32_t)v16[6] | ((uint32_t)v16[7] << 16);
        *(uint4*)(d_CTq + ((size_t)b * NP + qBase + q) * NP + pBase + p0) = o;
    }
}

// ================= fused softmin: 2 rows/warp, h cached in smem =================
__global__ void softmin_kernel(int src, int dst, float eps, int mode, int init, int use_max) {
    __shared__ float hs[NP];
    __shared__ double blkred[8];
    int bx = blockIdx.x;          // 1024 blocks
    int slice = bx >> 6;          // side*8 + b
    int side = slice >> 3;
    int b = slice & 7;
    int rowgrp = bx & 63;         // 64 groups of 16 rows
    int tid = threadIdx.x;
    int wid = tid >> 5, lane = tid & 31;

    float k2 = 1.4426950408889634f / eps;
    float qk = -IQSCALE * k2;
    const float* hsrc = (side == 0 ? (init ? d_gs : d_g[src])
                                   : (init ? d_fs : d_f[src])) + b * NP;
    for (int i = tid; i < NP; i += 256) {
        float h = hsrc[i];
        if (init) h = -9.0f * __logf(h);
        hs[i] = h * k2;
    }
    __syncthreads();

    int row0 = rowgrp * 16 + wid * 2;
    int idxA = b * NP + row0;
    const unsigned short* Cb = (side == 0 ? d_Cq : d_CTq);
    const uint4* rA = (const uint4*)(Cb + ((size_t)b * NP + row0) * NP);
    const uint4* rB = (const uint4*)(Cb + ((size_t)b * NP + row0 + 1) * NP);
    const float4* h4 = (const float4*)hs;

    float mA = 0.f, mB = 0.f;
    if (use_max) {
        float ma = -3.4e38f, mb = -3.4e38f;
        #pragma unroll
        for (int jj = 0; jj < 4; jj++) {
            uint4 qa = rA[jj * 32 + lane];
            uint4 qb = rB[jj * 32 + lane];
            float4 h0 = h4[(jj * 32 + lane) * 2];
            float4 h1 = h4[(jj * 32 + lane) * 2 + 1];
            ma = fmaxf(ma, fmaf((float)(qa.x & 0xFFFF), qk, h0.x));
            mb = fmaxf(mb, fmaf((float)(qb.x & 0xFFFF), qk, h0.x));
            ma = fmaxf(ma, fmaf((float)(qa.x >> 16),    qk, h0.y));
            mb = fmaxf(mb, fmaf((float)(qb.x >> 16),    qk, h0.y));
            ma = fmaxf(ma, fmaf((float)(qa.y & 0xFFFF), qk, h0.z));
            mb = fmaxf(mb, fmaf((float)(qb.y & 0xFFFF), qk, h0.z));
            ma = fmaxf(ma, fmaf((float)(qa.y >> 16),    qk, h0.w));
            mb = fmaxf(mb, fmaf((float)(qb.y >> 16),    qk, h0.w));
            ma = fmaxf(ma, fmaf((float)(qa.z & 0xFFFF), qk, h1.x));
            mb = fmaxf(mb, fmaf((float)(qb.z & 0xFFFF), qk, h1.x));
            ma = fmaxf(ma, fmaf((float)(qa.z >> 16),    qk, h1.y));
            mb = fmaxf(mb, fmaf((float)(qb.z >> 16),    qk, h1.y));
            ma = fmaxf(ma, fmaf((float)(qa.w & 0xFFFF), qk, h1.z));
            mb = fmaxf(mb, fmaf((float)(qb.w & 0xFFFF), qk, h1.z));
            ma = fmaxf(ma, fmaf((float)(qa.w >> 16),    qk, h1.w));
            mb = fmaxf(mb, fmaf((float)(qb.w >> 16),    qk, h1.w));
        }
        #pragma unroll
        for (int o = 16; o; o >>= 1) {
            ma = fmaxf(ma, __shfl_xor_sync(0xFFFFFFFFu, ma, o));
            mb = fmaxf(mb, __shfl_xor_sync(0xFFFFFFFFu, mb, o));
        }
        mA = ma; mB = mb;
    }

    float a0 = 0, a1 = 0, a2 = 0, a3 = 0;
    float b0 = 0, b1 = 0, b2 = 0, b3 = 0;
    #pragma unroll
    for (int jj = 0; jj < 4; jj++) {
        uint4 qa = rA[jj * 32 + lane];
        uint4 qb = rB[jj * 32 + lane];
        float4 h0 = h4[(jj * 32 + lane) * 2];
        float4 h1 = h4[(jj * 32 + lane) * 2 + 1];
        a0 += exp2f(fmaf((float)(qa.x & 0xFFFF), qk, h0.x) - mA);
        b0 += exp2f(fmaf((float)(qb.x & 0xFFFF), qk, h0.x) - mB);
        a1 += exp2f(fmaf((float)(qa.x >> 16),    qk, h0.y) - mA);
        b1 += exp2f(fmaf((float)(qb.x >> 16),    qk, h0.y) - mB);
        a2 += exp2f(fmaf((float)(qa.y & 0xFFFF), qk, h0.z) - mA);
        b2 += exp2f(fmaf((float)(qb.y & 0xFFFF), qk, h0.z) - mB);
        a3 += exp2f(fmaf((float)(qa.y >> 16),    qk, h0.w) - mA);
        b3 += exp2f(fmaf((float)(qb.y >> 16),    qk, h0.w) - mB);
        a0 += exp2f(fmaf((float)(qa.z & 0xFFFF), qk, h1.x) - mA);
        b0 += exp2f(fmaf((float)(qb.z & 0xFFFF), qk, h1.x) - mB);
        a1 += exp2f(fmaf((float)(qa.z >> 16),    qk, h1.y) - mA);
        b1 += exp2f(fmaf((float)(qb.z >> 16),    qk, h1.y) - mB);
        a2 += exp2f(fmaf((float)(qa.w & 0xFFFF), qk, h1.z) - mA);
        b2 += exp2f(fmaf((float)(qb.w & 0xFFFF), qk, h1.z) - mB);
        a3 += exp2f(fmaf((float)(qa.w >> 16),    qk, h1.w) - mA);
        b3 += exp2f(fmaf((float)(qb.w >> 16),    qk, h1.w) - mB);
    }
    float sumA = (a0 + a1) + (a2 + a3);
    float sumB = (b0 + b1) + (b2 + b3);
    #pragma unroll
    for (int o = 16; o; o >>= 1) {
        sumA += __shfl_xor_sync(0xFFFFFFFFu, sumA, o);
        sumB += __shfl_xor_sync(0xFFFFFFFFu, sumB, o);
    }

    const float ELN2 = 0.69314718055994531f;
    if (mode == 2) {
        if (lane == 0) {
            float vA = -eps * ELN2 * (mA + __log2f(sumA));
            float vB = -eps * ELN2 * (mB + __log2f(sumB));
            blkred[wid] = (double)(vA + vB);
        }
        __syncthreads();
        if (tid == 0) {
            double t = ((blkred[0] + blkred[1]) + (blkred[2] + blkred[3]))
                     + ((blkred[4] + blkred[5]) + (blkred[6] + blkred[7]));
            atomicAdd(&d_scon, t);
        }
    } else if (lane == 0) {
        float vA = -eps * ELN2 * (mA + __log2f(sumA));
        float vB = -eps * ELN2 * (mB + __log2f(sumB));
        float pA, pB;
        if (init) {
            const float* ps = (side == 0 ? d_fs : d_gs);
            pA = -9.0f * __logf(ps[idxA]);
            pB = -9.0f * __logf(ps[idxA + 1]);
        } else {
            const float* ps = (side == 0 ? d_f[src] : d_g[src]);
            pA = ps[idxA];
            pB = ps[idxA + 1];
        }
        float* pd = (side == 0 ? d_f[dst] : d_g[dst]);
        pd[idxA]     = 0.5f * (pA + vA);
        pd[idxA + 1] = 0.5f * (pB + vB);
    }
}

// ================= output =================
__global__ void write_out(float* out) {
    if (threadIdx.x == 0) {
        out[0] = (float)d_hinge;
        out[1] = (float)(d_scon / 8.0);
    }
}

// ================= launch =================
extern "C" void kernel_launch(void* const* d_in, const int* in_sizes, int n_in,
                              void* d_out, int out_size) {
    (void)in_sizes; (void)n_in; (void)out_size;
    const float* x1 = (const float*)d_in[0];
    const float* x2 = (const float*)d_in[1];
    const float* x3 = (const float*)d_in[2];
    const float* x4 = (const float*)d_in[3];
    float* out = (float*)d_out;

    double pexp = 2.0, diam = 3.0, blur = 0.05, scal = 0.5;
    float eps_list[16];
    int n_eps = 0;
    eps_list[n_eps++] = (float)pow(diam, pexp);
    for (double v = pexp * log(diam); v > pexp * log(blur); v += pexp * log(scal))
        eps_list[n_eps++] = (float)exp(v);
    eps_list[n_eps++] = (float)pow(blur, pexp);   // n_eps == 8

    cudaFuncSetAttribute(mma_gemm, cudaFuncAttributeMaxDynamicSharedMemorySize, SM_TOT);

    norm_split<<<6145, 256>>>(x1, x2, x3, x4);    // block 6144 = reset

    mma_gemm<<<dim3(8, 8, 32), 256, SM_TOT>>>();

    finalize_kernel<<<dim3(16, 16, NB), 256>>>(); // also produces init sums

    int cur = 0;
    for (int i = 0; i < n_eps; i++) {
        int init = (i == 0) ? 1 : 0;
        int use_max = (eps_list[i] < 0.02f) ? 1 : 0;
        softmin_kernel<<<1024, 256>>>(cur, 1 - cur, eps_list[i], 1, init, use_max);
        cur = 1 - cur;
    }
    softmin_kernel<<<1024, 256>>>(cur, cur, eps_list[n_eps - 1], 2, 0, 1);

    write_out<<<1, 1>>>(out);
}

// round 12
// speedup vs baseline: 1.2634x; 1.0952x over previous
#include <cuda_runtime.h>
#include <cuda_bf16.h>
#include <math.h>
#include <stdint.h>

#define NB 8
#define NP 1024
#define ND 64
#define GAMMA 10.0f
#define MARGIN 0.1f
#define QSCALE 65535.0f
#define IQSCALE (1.0f / 65535.0f)

// ================= device scratch =================
__device__ __nv_bfloat16 d_hi[6 * NB * NP * ND];
__device__ __nv_bfloat16 d_lo[2 * NB * NP * ND];     // lo only for x1n, x2n
__device__ float d_C[NB * NP * NP];                  // sim S (32 MB), dead after finalize
__device__ unsigned short d_Cq[NB * NP * NP];        // u16 cost (16 MB)
__device__ unsigned short d_CTq[NB * NP * NP];       // u16 transposed cost (16 MB)
__device__ float d_r[NB * NP];
__device__ float d_c[NB * NP];
__device__ float d_fs[NB * NP];                      // init row sums  e^{-C/9}
__device__ float d_gs[NB * NP];                      // init col sums  e^{-C/9}
__device__ float d_f[2][NB * NP];
__device__ float d_g[2][NB * NP];
__device__ double d_hinge;
__device__ double d_scon;

// ================= helpers =================
__device__ __forceinline__ uint32_t smem_u32(const void* p) {
    uint32_t a;
    asm("{ .reg .u64 t; cvta.to.shared.u64 t, %1; cvt.u32.u64 %0, t; }" : "=r"(a) : "l"(p));
    return a;
}
__device__ __forceinline__ uint32_t sw128(uint32_t off) { return off ^ ((off >> 3) & 0x70); }

__device__ __forceinline__ void ldsm_x4(uint32_t* r, uint32_t addr) {
    asm volatile("ldmatrix.sync.aligned.m8n8.x4.shared.b16 {%0,%1,%2,%3}, [%4];"
        : "=r"(r[0]), "=r"(r[1]), "=r"(r[2]), "=r"(r[3]) : "r"(addr));
}
__device__ __forceinline__ void ldsm_x2(uint32_t* r, uint32_t addr) {
    asm volatile("ldmatrix.sync.aligned.m8n8.x2.shared.b16 {%0,%1}, [%2];"
        : "=r"(r[0]), "=r"(r[1]) : "r"(addr));
}
__device__ __forceinline__ void mma_bf16(float* d, const uint32_t* a, const uint32_t* b) {
    asm volatile("mma.sync.aligned.m16n8k16.row.col.f32.bf16.bf16.f32 "
        "{%0,%1,%2,%3}, {%4,%5,%6,%7}, {%8,%9}, {%0,%1,%2,%3};"
        : "+f"(d[0]), "+f"(d[1]), "+f"(d[2]), "+f"(d[3])
        : "r"(a[0]), "r"(a[1]), "r"(a[2]), "r"(a[3]), "r"(b[0]), "r"(b[1]));
}
__device__ __forceinline__ unsigned short quant(float v) {
    return (unsigned short)__float2uint_rn(fminf(fmaxf(v, 0.f), 1.f) * QSCALE);
}

// ================= normalize + hi/lo split (block 6144 = reset) =================
__global__ void norm_split(const float* __restrict__ x1, const float* __restrict__ x2,
                           const float* __restrict__ x3, const float* __restrict__ x4) {
    if (blockIdx.x == 6144) {
        int tid = threadIdx.x;
        for (int i = tid; i < NB * NP; i += 256) {
            d_r[i] = 0.f; d_c[i] = 0.f; d_fs[i] = 0.f; d_gs[i] = 0.f;
        }
        if (tid == 0) { d_hinge = 0.0; d_scon = 0.0; }
        return;
    }
    int w = (blockIdx.x * 256 + threadIdx.x) >> 5;
    int lane = threadIdx.x & 31;
    int t = w / 8192;
    int row = w - t * 8192;
    const float* src = (t == 0) ? x1 : (t == 1) ? x2 : (t == 2 || t == 4) ? x3 : x4;
    float2 v = ((const float2*)(src + (size_t)row * ND))[lane];
    if (t < 4) {
        float ss = v.x * v.x + v.y * v.y;
        #pragma unroll
        for (int o = 16; o; o >>= 1) ss += __shfl_xor_sync(0xFFFFFFFFu, ss, o);
        float sc = 1.0f / fmaxf(sqrtf(ss), 1e-12f);
        v.x *= sc; v.y *= sc;
    }
    __nv_bfloat16 hx = __float2bfloat16(v.x);
    __nv_bfloat16 hy = __float2bfloat16(v.y);
    size_t base = ((size_t)t * 8192 + row) * ND;
    ((__nv_bfloat162*)(d_hi + base))[lane] = __nv_bfloat162(hx, hy);
    if (t < 2) {
        __nv_bfloat16 lx = __float2bfloat16(v.x - __bfloat162float(hx));
        __nv_bfloat16 ly = __float2bfloat16(v.y - __bfloat162float(hy));
        ((__nv_bfloat162*)(d_lo + base))[lane] = __nv_bfloat162(lx, ly);
    }
}

// ================= mma.sync fused GEMM =================
// job 0: TL (2 passes: Ahi*Bhi + Ahi*Blo) store S + r + c
// job 1: TR (1 pass) r only;  job 2: BL (1 pass) c only;  job 3: hinge (1 pass)
#define SM_AHI  0
#define SM_BHI  16384
#define SM_BLO  32768
#define SM_RED  49152
#define SM_TOT  (49152 + 256)

__global__ void __launch_bounds__(256, 2) mma_gemm() {
    extern __shared__ char smem[];
    uint32_t sb = smem_u32(smem);
    int tid = threadIdx.x;
    int wid = tid >> 5;
    int lane = tid & 31;
    int warp_m = wid >> 2;
    int warp_n = wid & 3;
    int z = blockIdx.z;
    int b = z & 7;
    int job = z >> 3;
    int rowBase = blockIdx.y * 128;
    int colBase = blockIdx.x * 128;

    const int TA[4] = {0, 0, 2, 4};
    const int TB[4] = {1, 3, 1, 5};
    {
        size_t aoff = ((size_t)TA[job] * 8192 + b * NP + rowBase) * ND;
        size_t boff = ((size_t)TB[job] * 8192 + b * NP + colBase) * ND;
        const uint4* sA = (const uint4*)(d_hi + aoff);
        const uint4* sB = (const uint4*)(d_hi + boff);
        #pragma unroll
        for (int it = 0; it < 4; it++) {
            int idx = it * 256 + tid;
            int r = idx >> 3, c = idx & 7;
            uint32_t so = sw128(r * 128 + c * 16);
            *(uint4*)(smem + SM_AHI + so) = sA[idx];
            *(uint4*)(smem + SM_BHI + so) = sB[idx];
        }
        if (job == 0) {
            const uint4* sBl = (const uint4*)(d_lo + boff);
            #pragma unroll
            for (int it = 0; it < 4; it++) {
                int idx = it * 256 + tid;
                int r = idx >> 3, c = idx & 7;
                uint32_t so = sw128(r * 128 + c * 16);
                *(uint4*)(smem + SM_BLO + so) = sBl[idx];
            }
        }
    }
    __syncthreads();

    float acc[4][4][4];
    #pragma unroll
    for (int mi = 0; mi < 4; mi++)
        #pragma unroll
        for (int ni = 0; ni < 4; ni++)
            #pragma unroll
            for (int v = 0; v < 4; v++) acc[mi][ni][v] = 0.f;

    int mrow = warp_m * 64 + (lane & 15);
    int nrow = warp_n * 32 + (lane & 7);
    int l7 = lane & 7;

    #pragma unroll
    for (int k = 0; k < 4; k++) {
        uint32_t Af[4][4], Bh[4][2], Bl[4][2];
        int achunk = (2 * k + (lane >> 4)) ^ l7;
        int bchunk = (2 * k + ((lane >> 3) & 1)) ^ l7;
        #pragma unroll
        for (int mi = 0; mi < 4; mi++)
            ldsm_x4(Af[mi], sb + SM_AHI + (mrow + mi * 16) * 128 + achunk * 16);
        #pragma unroll
        for (int ni = 0; ni < 4; ni++)
            ldsm_x2(Bh[ni], sb + SM_BHI + (nrow + ni * 8) * 128 + bchunk * 16);
        #pragma unroll
        for (int mi = 0; mi < 4; mi++)
            #pragma unroll
            for (int ni = 0; ni < 4; ni++)
                mma_bf16(acc[mi][ni], Af[mi], Bh[ni]);           // hi*hi
        if (job == 0) {
            #pragma unroll
            for (int ni = 0; ni < 4; ni++)
                ldsm_x2(Bl[ni], sb + SM_BLO + (nrow + ni * 8) * 128 + bchunk * 16);
            #pragma unroll
            for (int mi = 0; mi < 4; mi++)
                #pragma unroll
                for (int ni = 0; ni < 4; ni++)
                    mma_bf16(acc[mi][ni], Af[mi], Bl[ni]);       // hi*lo
        }
    }

    int g = lane >> 2, t4 = lane & 3;

    if (job == 3) {
        float h = 0.f;
        #pragma unroll
        for (int mi = 0; mi < 4; mi++)
            #pragma unroll
            for (int ni = 0; ni < 4; ni++)
                #pragma unroll
                for (int v = 0; v < 4; v++)
                    h += fmaxf(MARGIN - acc[mi][ni][v], 0.f);
        #pragma unroll
        for (int o = 16; o; o >>= 1) h += __shfl_xor_sync(0xFFFFFFFFu, h, o);
        float* red = (float*)(smem + SM_RED);
        if (lane == 0) red[wid] = h;
        __syncthreads();
        if (tid == 0) {
            float s = 0.f;
            #pragma unroll
            for (int w = 0; w < 8; w++) s += red[w];
            atomicAdd(&d_hinge, (double)s);
        }
        return;
    }

    float rs[4][2], cs[4][2];
    #pragma unroll
    for (int i = 0; i < 4; i++) { rs[i][0] = rs[i][1] = cs[i][0] = cs[i][1] = 0.f; }

    #pragma unroll
    for (int mi = 0; mi < 4; mi++) {
        int row = rowBase + warp_m * 64 + mi * 16 + g;
        #pragma unroll
        for (int ni = 0; ni < 4; ni++) {
            float e0 = __expf(GAMMA * acc[mi][ni][0]);
            float e1 = __expf(GAMMA * acc[mi][ni][1]);
            float e2 = __expf(GAMMA * acc[mi][ni][2]);
            float e3 = __expf(GAMMA * acc[mi][ni][3]);
            if (job == 0) {
                int col = colBase + warp_n * 32 + ni * 8 + t4 * 2;
                float* Cp = d_C + ((size_t)b * NP + row) * NP + col;
                *(float2*)Cp = make_float2(e0, e1);
                *(float2*)(Cp + (size_t)8 * NP) = make_float2(e2, e3);
            }
            rs[mi][0] += e0 + e1;  rs[mi][1] += e2 + e3;
            cs[ni][0] += e0 + e2;  cs[ni][1] += e1 + e3;
        }
    }

    if (job <= 1) {
        #pragma unroll
        for (int mi = 0; mi < 4; mi++) {
            float r0 = rs[mi][0], r1 = rs[mi][1];
            r0 += __shfl_xor_sync(0xFFFFFFFFu, r0, 1);
            r0 += __shfl_xor_sync(0xFFFFFFFFu, r0, 2);
            r1 += __shfl_xor_sync(0xFFFFFFFFu, r1, 1);
            r1 += __shfl_xor_sync(0xFFFFFFFFu, r1, 2);
            if (t4 == 0) {
                int row = rowBase + warp_m * 64 + mi * 16 + g;
                atomicAdd(&d_r[b * NP + row], r0);
                atomicAdd(&d_r[b * NP + row + 8], r1);
            }
        }
    }
    if (job == 0 || job == 2) {
        #pragma unroll
        for (int ni = 0; ni < 4; ni++) {
            float c0 = cs[ni][0], c1 = cs[ni][1];
            c0 += __shfl_xor_sync(0xFFFFFFFFu, c0, 4);
            c0 += __shfl_xor_sync(0xFFFFFFFFu, c0, 8);
            c0 += __shfl_xor_sync(0xFFFFFFFFu, c0, 16);
            c1 += __shfl_xor_sync(0xFFFFFFFFu, c1, 4);
            c1 += __shfl_xor_sync(0xFFFFFFFFu, c1, 8);
            c1 += __shfl_xor_sync(0xFFFFFFFFu, c1, 16);
            if (lane < 4) {
                int col = colBase + warp_n * 32 + ni * 8 + lane * 2;
                atomicAdd(&d_c[b * NP + col], c0);
                atomicAdd(&d_c[b * NP + col + 1], c1);
            }
        }
    }
}

// ================= finalize: C -> u16 Cq/CTq + fused init sums (conflict-free u16 tile) ====
__global__ void finalize_kernel() {
    __shared__ unsigned short tile[64][74];
    __shared__ float scol[64];
    int b = blockIdx.z;
    int pBase = blockIdx.y * 64, qBase = blockIdx.x * 64;
    int tid = threadIdx.x;  // 256
    int lane = tid & 31;
    const float NK9 = -0.16029948f;   // -log2(e)/9
    float cpart[4] = {0.f, 0.f, 0.f, 0.f};
    float rpart[4];
    if (tid < 64) scol[tid] = 0.f;
    __syncthreads();
    #pragma unroll
    for (int v = 0; v < 4; v++) {
        int f4 = v * 256 + tid;
        int row = f4 >> 4;
        int c4 = f4 & 15;
        int p = pBase + row;
        size_t idx = ((size_t)b * NP + p) * NP + qBase + c4 * 4;
        float4 S = *(const float4*)(d_C + idx);
        float rp = d_r[b * NP + p];
        float4 cq = *(const float4*)(d_c + b * NP + qBase + c4 * 4);
        float4 C;
        C.x = 1.f - __fdividef(S.x, rp + cq.x - S.x);
        C.y = 1.f - __fdividef(S.y, rp + cq.y - S.y);
        C.z = 1.f - __fdividef(S.z, rp + cq.z - S.z);
        C.w = 1.f - __fdividef(S.w, rp + cq.w - S.w);
        ushort4 q = make_ushort4(quant(C.x), quant(C.y), quant(C.z), quant(C.w));
        *(ushort4*)(d_Cq + idx) = q;
        ((ushort2*)&tile[row][c4 * 4])[0] = make_ushort2(q.x, q.y);
        ((ushort2*)&tile[row][c4 * 4])[1] = make_ushort2(q.z, q.w);
        float e0 = exp2f(C.x * NK9);
        float e1 = exp2f(C.y * NK9);
        float e2 = exp2f(C.z * NK9);
        float e3 = exp2f(C.w * NK9);
        rpart[v] = (e0 + e1) + (e2 + e3);
        cpart[0] += e0; cpart[1] += e1; cpart[2] += e2; cpart[3] += e3;
    }
    #pragma unroll
    for (int v = 0; v < 4; v++) {
        float r = rpart[v];
        r += __shfl_xor_sync(0xFFFFFFFFu, r, 1);
        r += __shfl_xor_sync(0xFFFFFFFFu, r, 2);
        r += __shfl_xor_sync(0xFFFFFFFFu, r, 4);
        r += __shfl_xor_sync(0xFFFFFFFFu, r, 8);
        if ((lane & 15) == 0)
            atomicAdd(&d_fs[b * NP + pBase + v * 16 + (tid >> 4)], r);
    }
    #pragma unroll
    for (int j = 0; j < 4; j++) {
        cpart[j] += __shfl_xor_sync(0xFFFFFFFFu, cpart[j], 16);
        if (lane < 16) atomicAdd(&scol[lane * 4 + j], cpart[j]);
    }
    __syncthreads();
    if (tid < 64) atomicAdd(&d_gs[b * NP + qBase + tid], scol[tid]);

    int q = tid >> 2;
    int sbase = tid & 3;
    #pragma unroll
    for (int cc0 = 0; cc0 < 2; cc0++) {
        int cc = sbase + cc0 * 4;
        int p0 = cc * 8;
        unsigned short v16[8];
        #pragma unroll
        for (int i = 0; i < 8; i++) v16[i] = tile[p0 + i][q];
        uint4 o;
        o.x = (uint32_t)v16[0] | ((uint32_t)v16[1] << 16);
        o.y = (uint32_t)v16[2] | ((uint32_t)v16[3] << 16);
        o.z = (uint32_t)v16[4] | ((uint32_t)v16[5] << 16);
        o.w = (uint32_t)v16[6] | ((uint32_t)v16[7] << 16);
        *(uint4*)(d_CTq + ((size_t)b * NP + qBase + q) * NP + pBase + p0) = o;
    }
}

// ================= fused softmin: templated, 2 rows/warp, h cached in smem =================
template <int INIT, int UMAX>
__global__ void softmin_kernel(int src, int dst, float eps, int mode) {
    __shared__ float hs[NP];
    __shared__ double blkred[8];
    int bx = blockIdx.x;          // 1024 blocks
    int slice = bx >> 6;
    int side = slice >> 3;
    int b = slice & 7;
    int rowgrp = bx & 63;
    int tid = threadIdx.x;
    int wid = tid >> 5, lane = tid & 31;

    float k2 = 1.4426950408889634f / eps;
    float qk = -IQSCALE * k2;
    const float* hsrc = (side == 0 ? (INIT ? d_gs : d_g[src])
                                   : (INIT ? d_fs : d_f[src])) + b * NP;
    for (int i = tid; i < NP; i += 256) {
        float h = hsrc[i];
        if (INIT) h = -9.0f * __logf(h);
        hs[i] = h * k2;
    }
    __syncthreads();

    int row0 = rowgrp * 16 + wid * 2;
    int idxA = b * NP + row0;
    const unsigned short* Cb = (side == 0 ? d_Cq : d_CTq);
    const uint4* rA = (const uint4*)(Cb + ((size_t)b * NP + row0) * NP);
    const uint4* rB = (const uint4*)(Cb + ((size_t)b * NP + row0 + 1) * NP);
    const float4* h4 = (const float4*)hs;

    float mA = 0.f, mB = 0.f;
    if (UMAX) {
        float ma = -3.4e38f, mb = -3.4e38f;
        #pragma unroll
        for (int jj = 0; jj < 4; jj++) {
            uint4 qa = rA[jj * 32 + lane];
            uint4 qb = rB[jj * 32 + lane];
            float4 h0 = h4[(jj * 32 + lane) * 2];
            float4 h1 = h4[(jj * 32 + lane) * 2 + 1];
            ma = fmaxf(ma, fmaf((float)(qa.x & 0xFFFF), qk, h0.x));
            mb = fmaxf(mb, fmaf((float)(qb.x & 0xFFFF), qk, h0.x));
            ma = fmaxf(ma, fmaf((float)(qa.x >> 16),    qk, h0.y));
            mb = fmaxf(mb, fmaf((float)(qb.x >> 16),    qk, h0.y));
            ma = fmaxf(ma, fmaf((float)(qa.y & 0xFFFF), qk, h0.z));
            mb = fmaxf(mb, fmaf((float)(qb.y & 0xFFFF), qk, h0.z));
            ma = fmaxf(ma, fmaf((float)(qa.y >> 16),    qk, h0.w));
            mb = fmaxf(mb, fmaf((float)(qb.y >> 16),    qk, h0.w));
            ma = fmaxf(ma, fmaf((float)(qa.z & 0xFFFF), qk, h1.x));
            mb = fmaxf(mb, fmaf((float)(qb.z & 0xFFFF), qk, h1.x));
            ma = fmaxf(ma, fmaf((float)(qa.z >> 16),    qk, h1.y));
            mb = fmaxf(mb, fmaf((float)(qb.z >> 16),    qk, h1.y));
            ma = fmaxf(ma, fmaf((float)(qa.w & 0xFFFF), qk, h1.z));
            mb = fmaxf(mb, fmaf((float)(qb.w & 0xFFFF), qk, h1.z));
            ma = fmaxf(ma, fmaf((float)(qa.w >> 16),    qk, h1.w));
            mb = fmaxf(mb, fmaf((float)(qb.w >> 16),    qk, h1.w));
        }
        #pragma unroll
        for (int o = 16; o; o >>= 1) {
            ma = fmaxf(ma, __shfl_xor_sync(0xFFFFFFFFu, ma, o));
            mb = fmaxf(mb, __shfl_xor_sync(0xFFFFFFFFu, mb, o));
        }
        mA = ma; mB = mb;
    }

    float a0 = 0, a1 = 0, a2 = 0, a3 = 0;
    float b0 = 0, b1 = 0, b2 = 0, b3 = 0;
    #pragma unroll
    for (int jj = 0; jj < 4; jj++) {
        uint4 qa = rA[jj * 32 + lane];
        uint4 qb = rB[jj * 32 + lane];
        float4 h0 = h4[(jj * 32 + lane) * 2];
        float4 h1 = h4[(jj * 32 + lane) * 2 + 1];
        a0 += exp2f(fmaf((float)(qa.x & 0xFFFF), qk, h0.x) - mA);
        b0 += exp2f(fmaf((float)(qb.x & 0xFFFF), qk, h0.x) - mB);
        a1 += exp2f(fmaf((float)(qa.x >> 16),    qk, h0.y) - mA);
        b1 += exp2f(fmaf((float)(qb.x >> 16),    qk, h0.y) - mB);
        a2 += exp2f(fmaf((float)(qa.y & 0xFFFF), qk, h0.z) - mA);
        b2 += exp2f(fmaf((float)(qb.y & 0xFFFF), qk, h0.z) - mB);
        a3 += exp2f(fmaf((float)(qa.y >> 16),    qk, h0.w) - mA);
        b3 += exp2f(fmaf((float)(qb.y >> 16),    qk, h0.w) - mB);
        a0 += exp2f(fmaf((float)(qa.z & 0xFFFF), qk, h1.x) - mA);
        b0 += exp2f(fmaf((float)(qb.z & 0xFFFF), qk, h1.x) - mB);
        a1 += exp2f(fmaf((float)(qa.z >> 16),    qk, h1.y) - mA);
        b1 += exp2f(fmaf((float)(qb.z >> 16),    qk, h1.y) - mB);
        a2 += exp2f(fmaf((float)(qa.w & 0xFFFF), qk, h1.z) - mA);
        b2 += exp2f(fmaf((float)(qb.w & 0xFFFF), qk, h1.z) - mB);
        a3 += exp2f(fmaf((float)(qa.w >> 16),    qk, h1.w) - mA);
        b3 += exp2f(fmaf((float)(qb.w >> 16),    qk, h1.w) - mB);
    }
    float sumA = (a0 + a1) + (a2 + a3);
    float sumB = (b0 + b1) + (b2 + b3);
    #pragma unroll
    for (int o = 16; o; o >>= 1) {
        sumA += __shfl_xor_sync(0xFFFFFFFFu, sumA, o);
        sumB += __shfl_xor_sync(0xFFFFFFFFu, sumB, o);
    }

    const float ELN2 = 0.69314718055994531f;
    if (mode == 2) {
        if (lane == 0) {
            float vA = -eps * ELN2 * (mA + __log2f(sumA));
            float vB = -eps * ELN2 * (mB + __log2f(sumB));
            blkred[wid] = (double)(vA + vB);
        }
        __syncthreads();
        if (tid == 0) {
            double t = ((blkred[0] + blkred[1]) + (blkred[2] + blkred[3]))
                     + ((blkred[4] + blkred[5]) + (blkred[6] + blkred[7]));
            atomicAdd(&d_scon, t);
        }
    } else if (lane == 0) {
        float vA = -eps * ELN2 * (mA + __log2f(sumA));
        float vB = -eps * ELN2 * (mB + __log2f(sumB));
        float pA, pB;
        if (INIT) {
            const float* ps = (side == 0 ? d_fs : d_gs);
            pA = -9.0f * __logf(ps[idxA]);
            pB = -9.0f * __logf(ps[idxA + 1]);
        } else {
            const float* ps = (side == 0 ? d_f[src] : d_g[src]);
            pA = ps[idxA];
            pB = ps[idxA + 1];
        }
        float* pd = (side == 0 ? d_f[dst] : d_g[dst]);
        pd[idxA]     = 0.5f * (pA + vA);
        pd[idxA + 1] = 0.5f * (pB + vB);
    }
}

// ================= output =================
__global__ void write_out(float* out) {
    if (threadIdx.x == 0) {
        out[0] = (float)d_hinge;
        out[1] = (float)(d_scon / 8.0);
    }
}

// ================= launch =================
extern "C" void kernel_launch(void* const* d_in, const int* in_sizes, int n_in,
                              void* d_out, int out_size) {
    (void)in_sizes; (void)n_in; (void)out_size;
    const float* x1 = (const float*)d_in[0];
    const float* x2 = (const float*)d_in[1];
    const float* x3 = (const float*)d_in[2];
    const float* x4 = (const float*)d_in[3];
    float* out = (float*)d_out;

    double pexp = 2.0, diam = 3.0, blur = 0.05, scal = 0.5;
    float eps_list[16];
    int n_eps = 0;
    eps_list[n_eps++] = (float)pow(diam, pexp);
    for (double v = pexp * log(diam); v > pexp * log(blur); v += pexp * log(scal))
        eps_list[n_eps++] = (float)exp(v);
    eps_list[n_eps++] = (float)pow(blur, pexp);   // n_eps == 8

    cudaFuncSetAttribute(mma_gemm, cudaFuncAttributeMaxDynamicSharedMemorySize, SM_TOT);

    norm_split<<<6145, 256>>>(x1, x2, x3, x4);    // block 6144 = reset

    mma_gemm<<<dim3(8, 8, 32), 256, SM_TOT>>>();

    finalize_kernel<<<dim3(16, 16, NB), 256>>>(); // also produces init sums

    int cur = 0;
    for (int i = 0; i < n_eps; i++) {
        float eps = eps_list[i];
        bool um = (eps < 0.02f);
        if (i == 0)      softmin_kernel<1, 0><<<1024, 256>>>(cur, 1 - cur, eps, 1);
        else if (!um)    softmin_kernel<0, 0><<<1024, 256>>>(cur, 1 - cur, eps, 1);
        else             softmin_kernel<0, 1><<<1024, 256>>>(cur, 1 - cur, eps, 1);
        cur = 1 - cur;
    }
    softmin_kernel<0, 1><<<1024, 256>>>(cur, cur, eps_list[n_eps - 1], 2);

    write_out<<<1, 1>>>(out);
}